// round 8
// baseline (speedup 1.0000x reference)
#include <cuda_runtime.h>
#include <cuda_bf16.h>
#include <cstdint>
#include <math.h>

#define B_ROWS 8192
#define HID    2048
#define INP    2048
#define NCLS   10
#define POOLK  45
#define NF     45
#define ESTD   270
#define WLD    2318   // W_lin leading dim (HID + ESTD)

// ---- GEMM tiling ----
#define BM 128
#define BN 64
#define BKS 32               // K per stage
#define NSTG_IT (INP / BKS)  // 64 stage iterations
#define LDK 36               // padded floats per smem row
#define SA_FLOATS (BM * LDK)           // 4608
#define SB_FLOATS (BN * LDK)           // 2304
#define STAGE_FLOATS (SA_FLOATS + SB_FLOATS)   // 6912 (27648 B)
#define NSTAGE 2
#define GEMM_SMEM_BYTES (NSTAGE * STAGE_FLOATS * 4)   // 55296 B -> 3 CTAs/SM
#define NTHREADS 256          // 8 warps: 4 M-groups x 2 N-groups, warp tile 32x32

// Scratch (device globals — no runtime allocation)
__device__ float  g_Y[(size_t)B_ROWS * HID];
__device__ float  g_Wl[NCLS * HID];              // W_lin[:, :2048] packed, aligned
__device__ float  g_WlE[NCLS * 288];             // W_lin[:, 2048:] packed (stride 288)
__device__ float  g_pooled[B_ROWS * NF];
__device__ float2 g_cs[B_ROWS * NF];

// ------------------------------------------------------------------
__device__ __forceinline__ uint32_t smem_u32(const void* p) {
    return (uint32_t)__cvta_generic_to_shared(p);
}
__device__ __forceinline__ void cp16(uint32_t dst, const void* src) {
    asm volatile("cp.async.cg.shared.global [%0], [%1], 16;\n" :: "r"(dst), "l"(src));
}
__device__ __forceinline__ void ldsm_x4(uint32_t& r0, uint32_t& r1, uint32_t& r2,
                                        uint32_t& r3, uint32_t addr) {
    asm volatile("ldmatrix.sync.aligned.m8n8.x4.shared.b16 {%0,%1,%2,%3}, [%4];"
                 : "=r"(r0), "=r"(r1), "=r"(r2), "=r"(r3) : "r"(addr));
}
__device__ __forceinline__ void mma_tf32(float* d, const uint32_t* a,
                                         uint32_t b0, uint32_t b1) {
    asm volatile(
        "mma.sync.aligned.m16n8k8.row.col.f32.tf32.tf32.f32 "
        "{%0,%1,%2,%3}, {%4,%5,%6,%7}, {%8,%9}, {%0,%1,%2,%3};"
        : "+f"(d[0]), "+f"(d[1]), "+f"(d[2]), "+f"(d[3])
        : "r"(a[0]), "r"(a[1]), "r"(a[2]), "r"(a[3]), "r"(b0), "r"(b1));
}
__device__ __forceinline__ float tanh_fast(float x) {
    float r;
    asm("tanh.approx.f32 %0, %1;" : "=f"(r) : "f"(x));
    return r;
}

// ------------------------------------------------------------------
// Kernel 0 (x3 slices): pack W_lin into aligned buffers
// ------------------------------------------------------------------
#define PREP_N (NCLS * HID + NCLS * ESTD)   // 23180
#define PREP_CH 7936
__global__ __launch_bounds__(256) void prep_wl_kernel(
    const float* __restrict__ Wl, int phase)
{
    int idx = phase * PREP_CH + blockIdx.x * 256 + threadIdx.x;
    int hi = (phase + 1) * PREP_CH; if (hi > PREP_N) hi = PREP_N;
    if (idx >= hi) return;
    int n1 = NCLS * HID;
    if (idx < n1) {
        int c = idx / HID, k = idx % HID;
        g_Wl[idx] = Wl[(size_t)c * WLD + k];
    } else {
        int j = idx - n1;
        int c = j / ESTD, e = j % ESTD;
        g_WlE[c * 288 + e] = Wl[(size_t)c * WLD + HID + e];
    }
}

// ------------------------------------------------------------------
// Kernel 1: Y = tanh(x @ W^T + b), tf32 mma.sync
// CTA 128x64, 8 warps (4M x 2N), warp tile 32x32, 2-stage cp.async,
// 3 CTAs per SM for cross-CTA pipe overlap
// ------------------------------------------------------------------
__device__ __forceinline__ void load_stage(
    float* sbase, const float* __restrict__ Ax, const float* __restrict__ Bw,
    int bm, int bn, int kt, int tid)
{
    uint32_t su = smem_u32(sbase);
    #pragma unroll
    for (int i = 0; i < 4; i++) {
        int ci = tid + i * NTHREADS;
        int r = ci >> 3, ko = (ci & 7) << 2;
        cp16(su + (uint32_t)(r * LDK + ko) * 4,
             Ax + (size_t)(bm + r) * INP + kt + ko);
    }
    uint32_t sub = su + SA_FLOATS * 4;
    #pragma unroll
    for (int i = 0; i < 2; i++) {
        int ci = tid + i * NTHREADS;
        int r = ci >> 3, ko = (ci & 7) << 2;
        cp16(sub + (uint32_t)(r * LDK + ko) * 4,
             Bw + (size_t)(bn + r) * INP + kt + ko);
    }
    asm volatile("cp.async.commit_group;" ::: "memory");
}

__global__ __launch_bounds__(NTHREADS, 3) void gemm_tanh_kernel(
    const float* __restrict__ x, const float* __restrict__ W,
    const float* __restrict__ b_ih, const float* __restrict__ b_hh)
{
    extern __shared__ float dsm[];
    __shared__ float sbias[BN];

    const int tid  = threadIdx.x;
    const int warp = tid >> 5;
    const int lane = tid & 31;
    const int qid  = lane >> 2;   // 0..7
    const int tq   = lane & 3;    // 0..3
    const int bm = blockIdx.y * BM;
    const int bn = blockIdx.x * BN;

    if (tid < BN) sbias[tid] = b_ih[bn + tid] + b_hh[bn + tid];

    const int wm = (warp & 3) * 32;    // 4 warps along M
    const int wn = (warp >> 2) * 32;   // 2 warps along N

    // ldmatrix source selectors (b16-as-tf32 trick)
    const int rsel = ((lane >> 3) & 1) * 8 + (lane & 7);
    const int csel = (lane >> 4) * 4;

    float acc[2][4][4];
    #pragma unroll
    for (int mf = 0; mf < 2; mf++)
        #pragma unroll
        for (int nf = 0; nf < 4; nf++)
            #pragma unroll
            for (int e = 0; e < 4; e++) acc[mf][nf][e] = 0.f;

    load_stage(dsm,                x, W, bm, bn, 0,   tid);
    load_stage(dsm + STAGE_FLOATS, x, W, bm, bn, BKS, tid);

    for (int s = 0; s < NSTG_IT; s++) {
        if (s >= NSTG_IT - 1)
            asm volatile("cp.async.wait_group 0;" ::: "memory");
        else
            asm volatile("cp.async.wait_group 1;" ::: "memory");
        __syncthreads();

        float* sA = dsm + (s & 1) * STAGE_FLOATS;
        uint32_t sAu = smem_u32(sA);
        const uint32_t* sB = (const uint32_t*)(sA + SA_FLOATS);

        #pragma unroll
        for (int kk = 0; kk < BKS; kk += 8) {
            uint32_t a[2][4], b[4][2];
            #pragma unroll
            for (int mf = 0; mf < 2; mf++) {
                uint32_t addr = sAu +
                    (uint32_t)((wm + mf * 16 + rsel) * LDK + kk + csel) * 4;
                ldsm_x4(a[mf][0], a[mf][1], a[mf][2], a[mf][3], addr);
            }
            #pragma unroll
            for (int nf = 0; nf < 4; nf++) {
                int rowb = (wn + nf * 8 + qid) * LDK + kk + tq;
                b[nf][0] = sB[rowb];
                b[nf][1] = sB[rowb + 4];
            }
            #pragma unroll
            for (int mf = 0; mf < 2; mf++)
                #pragma unroll
                for (int nf = 0; nf < 4; nf++)
                    mma_tf32(acc[mf][nf], a[mf], b[nf][0], b[nf][1]);
        }

        // prefetch stage s+2 into the buffer just freed (after all warps done)
        if (s + 2 < NSTG_IT) {
            __syncthreads();
            load_stage(dsm + (s & 1) * STAGE_FLOATS, x, W, bm, bn, (s + 2) * BKS, tid);
        }
    }

    // Epilogue: direct fragment -> global, bias + tanh
    #pragma unroll
    for (int mf = 0; mf < 2; mf++) {
        int r0 = bm + wm + mf * 16 + qid;
        #pragma unroll
        for (int nf = 0; nf < 4; nf++) {
            int lc = wn + nf * 8 + tq * 2;
            float b0 = sbias[lc], b1 = sbias[lc + 1];
            float2 v0, v1;
            v0.x = tanh_fast(acc[mf][nf][0] + b0);
            v0.y = tanh_fast(acc[mf][nf][1] + b1);
            v1.x = tanh_fast(acc[mf][nf][2] + b0);
            v1.y = tanh_fast(acc[mf][nf][3] + b1);
            *(float2*)&g_Y[(size_t)r0 * HID + bn + lc] = v0;
            *(float2*)&g_Y[(size_t)(r0 + 8) * HID + bn + lc] = v1;
        }
    }
}

// ------------------------------------------------------------------
// Kernel 2: pooled[b,f] = mean_{j<45} Y[b, f*45+j]  (float4 loads)
// ------------------------------------------------------------------
__global__ __launch_bounds__(128) void pool_kernel()
{
    __shared__ float s[HID];
    const int b = blockIdx.x, t = threadIdx.x;
    const float4* Yr = (const float4*)&g_Y[(size_t)b * HID];
    #pragma unroll
    for (int i = 0; i < 4; i++) {
        float4 v = Yr[t + i * 128];
        *(float4*)&s[(t + i * 128) * 4] = v;
    }
    __syncthreads();
    if (t < NF) {
        float sum = 0.f;
        #pragma unroll
        for (int j = 0; j < POOLK; j++) sum += s[t * POOLK + j];
        g_pooled[b * NF + t] = sum * (1.0f / (float)POOLK);
    }
}

// ------------------------------------------------------------------
// Kernel 3: per-feature inclusive scan of (v, v^2) over batch
// ------------------------------------------------------------------
__global__ __launch_bounds__(256) void scan_kernel()
{
    const int f = blockIdx.x;
    const int t = threadIdx.x, lane = t & 31, w = t >> 5;
    __shared__ float2 wtot[8];
    float2 carry = make_float2(0.f, 0.f);

    for (int chunk = 0; chunk < B_ROWS / 256; chunk++) {
        int i = chunk * 256 + t;
        float v = g_pooled[i * NF + f];
        float2 s = make_float2(v, v * v);
        #pragma unroll
        for (int off = 1; off < 32; off <<= 1) {
            float a  = __shfl_up_sync(0xffffffffu, s.x, off);
            float b2 = __shfl_up_sync(0xffffffffu, s.y, off);
            if (lane >= off) { s.x += a; s.y += b2; }
        }
        if (lane == 31) wtot[w] = s;
        __syncthreads();
        if (w == 0 && lane < 8) {
            float2 xx = wtot[lane];
            #pragma unroll
            for (int off = 1; off < 8; off <<= 1) {
                float a  = __shfl_up_sync(0xffu, xx.x, off);
                float b2 = __shfl_up_sync(0xffu, xx.y, off);
                if (lane >= off) { xx.x += a; xx.y += b2; }
            }
            wtot[lane] = xx;
        }
        __syncthreads();
        float2 pre = carry;
        if (w > 0) { pre.x += wtot[w - 1].x; pre.y += wtot[w - 1].y; }
        g_cs[i * NF + f] = make_float2(s.x + pre.x, s.y + pre.y);
        carry.x += wtot[7].x;
        carry.y += wtot[7].y;
        __syncthreads();
    }
}

// ------------------------------------------------------------------
// Kernel 4: logits + softmax — warp per row, float4 loads
// ------------------------------------------------------------------
__global__ __launch_bounds__(256) void logits_kernel(
    const float* __restrict__ b_lin, float* __restrict__ out)
{
    const int t = threadIdx.x, lane = t & 31, wid = t >> 5;
    __shared__ float est_s[8][272];

    for (int e = t; e < 8 * ESTD; e += 256) {
        int r = e / ESTD, e2 = e % ESTD;
        int f = e2 / 6, rem = e2 % 6, j = rem >> 1, sflag = rem & 1;
        int L = (j == 0) ? 32 : (j == 1) ? 128 : 512;
        int bb = blockIdx.x * 8 + r;
        float2 c1 = g_cs[bb * NF + f];
        float2 c0 = (bb >= L) ? g_cs[(bb - L) * NF + f] : make_float2(0.f, 0.f);
        float cnt = fminf((float)(bb + 1), (float)L);
        float m = (c1.x - c0.x) / cnt;
        est_s[r][e2] = (sflag == 0) ? m : ((c1.y - c0.y) / cnt - m * m);
    }
    __syncthreads();

    const int row = blockIdx.x * 8 + wid;
    const float4* Yrow = (const float4*)&g_Y[(size_t)row * HID];

    float acc[NCLS];
    #pragma unroll
    for (int c = 0; c < NCLS; c++) acc[c] = 0.f;

    #pragma unroll
    for (int j = 0; j < 16; j++) {
        int k4 = j * 32 + lane;
        float4 y = Yrow[k4];
        #pragma unroll
        for (int c = 0; c < NCLS; c++) {
            float4 w = ((const float4*)(g_Wl + c * HID))[k4];
            acc[c] += y.x * w.x + y.y * w.y + y.z * w.z + y.w * w.w;
        }
    }
    for (int e = lane; e < ESTD; e += 32) {
        float ev = est_s[wid][e];
        #pragma unroll
        for (int c = 0; c < NCLS; c++) acc[c] += ev * g_WlE[c * 288 + e];
    }
    #pragma unroll
    for (int c = 0; c < NCLS; c++) {
        #pragma unroll
        for (int off = 16; off > 0; off >>= 1)
            acc[c] += __shfl_down_sync(0xffffffffu, acc[c], off);
    }
    if (lane == 0) {
        float lg[NCLS], mx = -1e30f;
        #pragma unroll
        for (int c = 0; c < NCLS; c++) { lg[c] = acc[c] + b_lin[c]; mx = fmaxf(mx, lg[c]); }
        float sum = 0.f;
        #pragma unroll
        for (int c = 0; c < NCLS; c++) { lg[c] = expf(lg[c] - mx); sum += lg[c]; }
        float inv = 1.0f / sum;
        #pragma unroll
        for (int c = 0; c < NCLS; c++) out[row * NCLS + c] = lg[c] * inv;
    }
}

// ------------------------------------------------------------------
extern "C" void kernel_launch(void* const* d_in, const int* in_sizes, int n_in,
                              void* d_out, int out_size)
{
    (void)in_sizes; (void)n_in; (void)out_size;
    const float* x     = (const float*)d_in[0];
    const float* W_ih  = (const float*)d_in[1];
    // d_in[2] = W_hh — dead: seq_len==1 and h0==0
    const float* b_ih  = (const float*)d_in[3];
    const float* b_hh  = (const float*)d_in[4];
    const float* W_lin = (const float*)d_in[5];
    const float* b_lin = (const float*)d_in[6];
    float* out = (float*)d_out;

    cudaFuncSetAttribute(gemm_tanh_kernel,
                         cudaFuncAttributeMaxDynamicSharedMemorySize, GEMM_SMEM_BYTES);

    // GEMM kept as 4th launch (ncu capture slot)
    int pb = (PREP_CH + 255) / 256;
    prep_wl_kernel<<<pb, 256>>>(W_lin, 0);
    prep_wl_kernel<<<pb, 256>>>(W_lin, 1);
    prep_wl_kernel<<<pb, 256>>>(W_lin, 2);

    dim3 g1(HID / BN, B_ROWS / BM);   // 32 x 64 = 2048 CTAs, 3 per SM
    gemm_tanh_kernel<<<g1, NTHREADS, GEMM_SMEM_BYTES>>>(x, W_ih, b_ih, b_hh);

    pool_kernel<<<B_ROWS, 128>>>();
    scan_kernel<<<NF, 256>>>();
    logits_kernel<<<B_ROWS / 8, 256>>>(b_lin, out);
}

// round 9
// speedup vs baseline: 1.1203x; 1.1203x over previous
#include <cuda_runtime.h>
#include <cuda_bf16.h>
#include <cstdint>
#include <math.h>

#define B_ROWS 8192
#define HID    2048
#define INP    2048
#define NCLS   10
#define POOLK  45
#define NF     45
#define ESTD   270
#define WLD    2318   // W_lin leading dim (HID + ESTD)

// ---- GEMM tiling (R6 shape: the measured optimum) ----
#define BM 128
#define BN 128
#define BKS 32               // K per stage
#define NSTG_IT (INP / BKS)  // 64 stage iterations
#define LDK 36               // padded floats per smem row
#define SA_FLOATS (BM * LDK)           // 4608
#define SB_FLOATS (BN * LDK)           // 4608
#define STAGE_FLOATS (SA_FLOATS + SB_FLOATS)   // 9216 (36864 B)
#define NSTAGE 3
#define GEMM_SMEM_BYTES (NSTAGE * STAGE_FLOATS * 4)   // 110592 B -> 2 CTAs/SM
#define NTHREADS 256          // 8 warps: 2 M-groups x 4 N-groups, warp tile 64x32

// Scratch (device globals — no runtime allocation)
__device__ float  g_Y[(size_t)B_ROWS * HID];
__device__ float  g_Wl[NCLS * HID];              // W_lin[:, :2048] packed, aligned
__device__ float  g_WlE[NCLS * 288];             // W_lin[:, 2048:] packed (stride 288)
__device__ float  g_pooled[B_ROWS * NF];
__device__ float2 g_cs[B_ROWS * NF];

// ------------------------------------------------------------------
__device__ __forceinline__ uint32_t smem_u32(const void* p) {
    return (uint32_t)__cvta_generic_to_shared(p);
}
__device__ __forceinline__ void cp16(uint32_t dst, const void* src) {
    asm volatile("cp.async.cg.shared.global [%0], [%1], 16;\n" :: "r"(dst), "l"(src));
}
__device__ __forceinline__ void ldsm_x4(uint32_t& r0, uint32_t& r1, uint32_t& r2,
                                        uint32_t& r3, uint32_t addr) {
    asm volatile("ldmatrix.sync.aligned.m8n8.x4.shared.b16 {%0,%1,%2,%3}, [%4];"
                 : "=r"(r0), "=r"(r1), "=r"(r2), "=r"(r3) : "r"(addr));
}
__device__ __forceinline__ void mma_tf32(float* d, const uint32_t* a,
                                         uint32_t b0, uint32_t b1) {
    asm volatile(
        "mma.sync.aligned.m16n8k8.row.col.f32.tf32.tf32.f32 "
        "{%0,%1,%2,%3}, {%4,%5,%6,%7}, {%8,%9}, {%0,%1,%2,%3};"
        : "+f"(d[0]), "+f"(d[1]), "+f"(d[2]), "+f"(d[3])
        : "r"(a[0]), "r"(a[1]), "r"(a[2]), "r"(a[3]), "r"(b0), "r"(b1));
}
__device__ __forceinline__ float tanh_fast(float x) {
    float r;
    asm("tanh.approx.f32 %0, %1;" : "=f"(r) : "f"(x));
    return r;
}

// ------------------------------------------------------------------
// Kernel 0 (x3 slices): pack W_lin into aligned buffers
// ------------------------------------------------------------------
#define PREP_N (NCLS * HID + NCLS * ESTD)   // 23180
#define PREP_CH 7936
__global__ __launch_bounds__(256) void prep_wl_kernel(
    const float* __restrict__ Wl, int phase)
{
    int idx = phase * PREP_CH + blockIdx.x * 256 + threadIdx.x;
    int hi = (phase + 1) * PREP_CH; if (hi > PREP_N) hi = PREP_N;
    if (idx >= hi) return;
    int n1 = NCLS * HID;
    if (idx < n1) {
        int c = idx / HID, k = idx % HID;
        g_Wl[idx] = Wl[(size_t)c * WLD + k];
    } else {
        int j = idx - n1;
        int c = j / ESTD, e = j % ESTD;
        g_WlE[c * 288 + e] = Wl[(size_t)c * WLD + HID + e];
    }
}

// ------------------------------------------------------------------
// Kernel 1: Y = tanh(x @ W^T + b), tf32 mma.sync
// CTA 128x128, 8 warps (2M x 4N), warp tile 64x32, 3-stage cp.async,
// 2 CTAs/SM, fragment double-buffering (k8-step software pipeline)
// ------------------------------------------------------------------
__device__ __forceinline__ void load_stage(
    float* sbase, const float* __restrict__ Ax, const float* __restrict__ Bw,
    int bm, int bn, int kt, int tid)
{
    uint32_t su = smem_u32(sbase);
    #pragma unroll
    for (int i = 0; i < 4; i++) {
        int ci = tid + i * NTHREADS;
        int r = ci >> 3, ko = (ci & 7) << 2;
        cp16(su + (uint32_t)(r * LDK + ko) * 4,
             Ax + (size_t)(bm + r) * INP + kt + ko);
    }
    uint32_t sub = su + SA_FLOATS * 4;
    #pragma unroll
    for (int i = 0; i < 4; i++) {
        int ci = tid + i * NTHREADS;
        int r = ci >> 3, ko = (ci & 7) << 2;
        cp16(sub + (uint32_t)(r * LDK + ko) * 4,
             Bw + (size_t)(bn + r) * INP + kt + ko);
    }
    asm volatile("cp.async.commit_group;" ::: "memory");
}

__global__ __launch_bounds__(NTHREADS, 2) void gemm_tanh_kernel(
    const float* __restrict__ x, const float* __restrict__ W,
    const float* __restrict__ b_ih, const float* __restrict__ b_hh)
{
    extern __shared__ float dsm[];
    __shared__ float sbias[BN];

    const int tid  = threadIdx.x;
    const int warp = tid >> 5;
    const int lane = tid & 31;
    const int qid  = lane >> 2;   // 0..7
    const int tq   = lane & 3;    // 0..3
    const int bm = blockIdx.y * BM;
    const int bn = blockIdx.x * BN;

    if (tid < BN) sbias[tid] = b_ih[bn + tid] + b_hh[bn + tid];

    const int wm = (warp & 1) * 64;    // 2 warps along M
    const int wn = (warp >> 1) * 32;   // 4 warps along N

    // ldmatrix source selectors (b16-as-tf32 trick)
    const int rsel = ((lane >> 3) & 1) * 8 + (lane & 7);
    const int csel = (lane >> 4) * 4;

    float acc[4][4][4];
    #pragma unroll
    for (int mf = 0; mf < 4; mf++)
        #pragma unroll
        for (int nf = 0; nf < 4; nf++)
            #pragma unroll
            for (int e = 0; e < 4; e++) acc[mf][nf][e] = 0.f;

    load_stage(dsm,                x, W, bm, bn, 0,   tid);
    load_stage(dsm + STAGE_FLOATS, x, W, bm, bn, BKS, tid);

    // double-buffered fragments
    uint32_t af[2][4][4], bf[2][4][2];

    int sidx = 0;
    for (int s = 0; s < NSTG_IT; s++) {
        if (s == NSTG_IT - 1)
            asm volatile("cp.async.wait_group 0;" ::: "memory");
        else
            asm volatile("cp.async.wait_group 1;" ::: "memory");
        __syncthreads();

        // prefetch into stage (s+2)%3 — its readers finished before the barrier above
        if (s + 2 < NSTG_IT) {
            int nidx = sidx + 2; if (nidx >= NSTAGE) nidx -= NSTAGE;
            load_stage(dsm + nidx * STAGE_FLOATS, x, W, bm, bn, (s + 2) * BKS, tid);
        }

        float* sA = dsm + sidx * STAGE_FLOATS;
        uint32_t sAu = smem_u32(sA);
        const uint32_t* sB = (const uint32_t*)(sA + SA_FLOATS);

        // preload fragments for kk = 0
        #pragma unroll
        for (int mf = 0; mf < 4; mf++) {
            uint32_t addr = sAu + (uint32_t)((wm + mf * 16 + rsel) * LDK + csel) * 4;
            ldsm_x4(af[0][mf][0], af[0][mf][1], af[0][mf][2], af[0][mf][3], addr);
        }
        #pragma unroll
        for (int nf = 0; nf < 4; nf++) {
            int rowb = (wn + nf * 8 + qid) * LDK + tq;
            bf[0][nf][0] = sB[rowb];
            bf[0][nf][1] = sB[rowb + 4];
        }

        #pragma unroll
        for (int k8 = 0; k8 < 4; k8++) {
            const int cur = k8 & 1, nxt = cur ^ 1;
            // issue loads for the NEXT k8-step before consuming the current one
            if (k8 < 3) {
                const int kk = (k8 + 1) * 8;
                #pragma unroll
                for (int mf = 0; mf < 4; mf++) {
                    uint32_t addr = sAu +
                        (uint32_t)((wm + mf * 16 + rsel) * LDK + kk + csel) * 4;
                    ldsm_x4(af[nxt][mf][0], af[nxt][mf][1],
                            af[nxt][mf][2], af[nxt][mf][3], addr);
                }
                #pragma unroll
                for (int nf = 0; nf < 4; nf++) {
                    int rowb = (wn + nf * 8 + qid) * LDK + kk + tq;
                    bf[nxt][nf][0] = sB[rowb];
                    bf[nxt][nf][1] = sB[rowb + 4];
                }
            }
            // HMMAs for the current step overlap the loads above
            #pragma unroll
            for (int mf = 0; mf < 4; mf++)
                #pragma unroll
                for (int nf = 0; nf < 4; nf++)
                    mma_tf32(acc[mf][nf], af[cur][mf], bf[cur][nf][0], bf[cur][nf][1]);
        }

        if (++sidx >= NSTAGE) sidx = 0;
        // no trailing __syncthreads: next iteration's barrier orders reuse
    }

    // Epilogue: direct fragment -> global, bias + tanh
    #pragma unroll
    for (int mf = 0; mf < 4; mf++) {
        int r0 = bm + wm + mf * 16 + qid;
        #pragma unroll
        for (int nf = 0; nf < 4; nf++) {
            int lc = wn + nf * 8 + tq * 2;
            float b0 = sbias[lc], b1 = sbias[lc + 1];
            float2 v0, v1;
            v0.x = tanh_fast(acc[mf][nf][0] + b0);
            v0.y = tanh_fast(acc[mf][nf][1] + b1);
            v1.x = tanh_fast(acc[mf][nf][2] + b0);
            v1.y = tanh_fast(acc[mf][nf][3] + b1);
            *(float2*)&g_Y[(size_t)r0 * HID + bn + lc] = v0;
            *(float2*)&g_Y[(size_t)(r0 + 8) * HID + bn + lc] = v1;
        }
    }
}

// ------------------------------------------------------------------
// Kernel 2: pooled[b,f] = mean_{j<45} Y[b, f*45+j]  (float4 loads)
// ------------------------------------------------------------------
__global__ __launch_bounds__(128) void pool_kernel()
{
    __shared__ float s[HID];
    const int b = blockIdx.x, t = threadIdx.x;
    const float4* Yr = (const float4*)&g_Y[(size_t)b * HID];
    #pragma unroll
    for (int i = 0; i < 4; i++) {
        float4 v = Yr[t + i * 128];
        *(float4*)&s[(t + i * 128) * 4] = v;
    }
    __syncthreads();
    if (t < NF) {
        float sum = 0.f;
        #pragma unroll
        for (int j = 0; j < POOLK; j++) sum += s[t * POOLK + j];
        g_pooled[b * NF + t] = sum * (1.0f / (float)POOLK);
    }
}

// ------------------------------------------------------------------
// Kernel 3: per-feature inclusive scan of (v, v^2) over batch
// ------------------------------------------------------------------
__global__ __launch_bounds__(256) void scan_kernel()
{
    const int f = blockIdx.x;
    const int t = threadIdx.x, lane = t & 31, w = t >> 5;
    __shared__ float2 wtot[8];
    float2 carry = make_float2(0.f, 0.f);

    for (int chunk = 0; chunk < B_ROWS / 256; chunk++) {
        int i = chunk * 256 + t;
        float v = g_pooled[i * NF + f];
        float2 s = make_float2(v, v * v);
        #pragma unroll
        for (int off = 1; off < 32; off <<= 1) {
            float a  = __shfl_up_sync(0xffffffffu, s.x, off);
            float b2 = __shfl_up_sync(0xffffffffu, s.y, off);
            if (lane >= off) { s.x += a; s.y += b2; }
        }
        if (lane == 31) wtot[w] = s;
        __syncthreads();
        if (w == 0 && lane < 8) {
            float2 xx = wtot[lane];
            #pragma unroll
            for (int off = 1; off < 8; off <<= 1) {
                float a  = __shfl_up_sync(0xffu, xx.x, off);
                float b2 = __shfl_up_sync(0xffu, xx.y, off);
                if (lane >= off) { xx.x += a; xx.y += b2; }
            }
            wtot[lane] = xx;
        }
        __syncthreads();
        float2 pre = carry;
        if (w > 0) { pre.x += wtot[w - 1].x; pre.y += wtot[w - 1].y; }
        g_cs[i * NF + f] = make_float2(s.x + pre.x, s.y + pre.y);
        carry.x += wtot[7].x;
        carry.y += wtot[7].y;
        __syncthreads();
    }
}

// ------------------------------------------------------------------
// Kernel 4: logits + softmax — warp per row, float4 loads
// ------------------------------------------------------------------
__global__ __launch_bounds__(256) void logits_kernel(
    const float* __restrict__ b_lin, float* __restrict__ out)
{
    const int t = threadIdx.x, lane = t & 31, wid = t >> 5;
    __shared__ float est_s[8][272];

    for (int e = t; e < 8 * ESTD; e += 256) {
        int r = e / ESTD, e2 = e % ESTD;
        int f = e2 / 6, rem = e2 % 6, j = rem >> 1, sflag = rem & 1;
        int L = (j == 0) ? 32 : (j == 1) ? 128 : 512;
        int bb = blockIdx.x * 8 + r;
        float2 c1 = g_cs[bb * NF + f];
        float2 c0 = (bb >= L) ? g_cs[(bb - L) * NF + f] : make_float2(0.f, 0.f);
        float cnt = fminf((float)(bb + 1), (float)L);
        float m = (c1.x - c0.x) / cnt;
        est_s[r][e2] = (sflag == 0) ? m : ((c1.y - c0.y) / cnt - m * m);
    }
    __syncthreads();

    const int row = blockIdx.x * 8 + wid;
    const float4* Yrow = (const float4*)&g_Y[(size_t)row * HID];

    float acc[NCLS];
    #pragma unroll
    for (int c = 0; c < NCLS; c++) acc[c] = 0.f;

    #pragma unroll
    for (int j = 0; j < 16; j++) {
        int k4 = j * 32 + lane;
        float4 y = Yrow[k4];
        #pragma unroll
        for (int c = 0; c < NCLS; c++) {
            float4 w = ((const float4*)(g_Wl + c * HID))[k4];
            acc[c] += y.x * w.x + y.y * w.y + y.z * w.z + y.w * w.w;
        }
    }
    for (int e = lane; e < ESTD; e += 32) {
        float ev = est_s[wid][e];
        #pragma unroll
        for (int c = 0; c < NCLS; c++) acc[c] += ev * g_WlE[c * 288 + e];
    }
    #pragma unroll
    for (int c = 0; c < NCLS; c++) {
        #pragma unroll
        for (int off = 16; off > 0; off >>= 1)
            acc[c] += __shfl_down_sync(0xffffffffu, acc[c], off);
    }
    if (lane == 0) {
        float lg[NCLS], mx = -1e30f;
        #pragma unroll
        for (int c = 0; c < NCLS; c++) { lg[c] = acc[c] + b_lin[c]; mx = fmaxf(mx, lg[c]); }
        float sum = 0.f;
        #pragma unroll
        for (int c = 0; c < NCLS; c++) { lg[c] = expf(lg[c] - mx); sum += lg[c]; }
        float inv = 1.0f / sum;
        #pragma unroll
        for (int c = 0; c < NCLS; c++) out[row * NCLS + c] = lg[c] * inv;
    }
}

// ------------------------------------------------------------------
extern "C" void kernel_launch(void* const* d_in, const int* in_sizes, int n_in,
                              void* d_out, int out_size)
{
    (void)in_sizes; (void)n_in; (void)out_size;
    const float* x     = (const float*)d_in[0];
    const float* W_ih  = (const float*)d_in[1];
    // d_in[2] = W_hh — dead: seq_len==1 and h0==0
    const float* b_ih  = (const float*)d_in[3];
    const float* b_hh  = (const float*)d_in[4];
    const float* W_lin = (const float*)d_in[5];
    const float* b_lin = (const float*)d_in[6];
    float* out = (float*)d_out;

    cudaFuncSetAttribute(gemm_tanh_kernel,
                         cudaFuncAttributeMaxDynamicSharedMemorySize, GEMM_SMEM_BYTES);

    // GEMM kept as 4th launch (ncu capture slot)
    int pb = (PREP_CH + 255) / 256;
    prep_wl_kernel<<<pb, 256>>>(W_lin, 0);
    prep_wl_kernel<<<pb, 256>>>(W_lin, 1);
    prep_wl_kernel<<<pb, 256>>>(W_lin, 2);

    dim3 g1(HID / BN, B_ROWS / BM);   // 16 x 64 = 1024 CTAs, 2 per SM
    gemm_tanh_kernel<<<g1, NTHREADS, GEMM_SMEM_BYTES>>>(x, W_ih, b_ih, b_hh);

    pool_kernel<<<B_ROWS, 128>>>();
    scan_kernel<<<NF, 256>>>();
    logits_kernel<<<B_ROWS / 8, 256>>>(b_lin, out);
}